// round 1
// baseline (speedup 1.0000x reference)
#include <cuda_runtime.h>

#define TT 3
#define FF 17
#define NN 8
#define DT 0.2f
#define EPS 1e-8f

__device__ float g_attr_dl[8];

// ---------------------------------------------------------------------------
// Precompute: dur[n] depends only on ego[1] (fixed batch index in reference!)
// dur[n] = sum_t isin(ego[1,-1,8+n], ego[1,t,8:16]); then run the dl MLP on it.
// ---------------------------------------------------------------------------
__global__ void sfm_precompute(const float* __restrict__ ego,
                               const float* __restrict__ dl_wi,
                               const float* __restrict__ dl_bi,
                               const float* __restrict__ dl_wo,
                               const float* __restrict__ dl_bo)
{
    int n = threadIdx.x;
    if (n >= 8) return;
    const float* e1 = ego + (size_t)1 * TT * FF;   // batch row 1
    float id = e1[(TT - 1) * FF + 8 + n];
    float dur = 0.f;
#pragma unroll
    for (int t = 0; t < TT; t++) {
        bool found = false;
#pragma unroll
        for (int k = 0; k < 8; k++)
            found = found || (e1[t * FF + 8 + k] == id);
        dur += found ? 1.f : 0.f;
    }
    float acc = dl_bo[0];
#pragma unroll
    for (int j = 0; j < 32; j++) {
        float h = fmaxf(-(dl_wi[j] * dur + dl_bi[j]), 0.f);  // relu(-(wi*x+bi))
        acc = fmaf(dl_wo[j], h, acc);
    }
    g_attr_dl[n] = acc;
}

// ---------------------------------------------------------------------------
// Main kernel: one thread per agent.
// ---------------------------------------------------------------------------
__global__ void __launch_bounds__(256) sfm_main(
    const float* __restrict__ ego, const float* __restrict__ nei,
    const float* __restrict__ border, const float* __restrict__ adp,
    const float* __restrict__ eff_angle,
    const float* __restrict__ an_wi, const float* __restrict__ an_bi,
    const float* __restrict__ an_wo, const float* __restrict__ an_bo,
    const float* __restrict__ rn_wi, const float* __restrict__ rn_bi,
    const float* __restrict__ rn_wo, const float* __restrict__ rn_bo,
    const float* __restrict__ rb_wi, const float* __restrict__ rb_bi,
    const float* __restrict__ rb_wo, const float* __restrict__ rb_bo,
    float* __restrict__ out, int n_batch)
{
    // negated wi/bi so relu(-(wi*x+bi)) == max(fma(nwi, x, nbi), 0)
    __shared__ float sw[9][32];
    __shared__ float sdl[8];
    int tid = threadIdx.x;
    if (tid < 32)       { sw[0][tid] = -an_wi[tid]; sw[1][tid] = -an_bi[tid]; sw[2][tid] = an_wo[tid]; }
    else if (tid < 64)  { int j = tid - 32; sw[3][j] = -rn_wi[j]; sw[4][j] = -rn_bi[j]; sw[5][j] = rn_wo[j]; }
    else if (tid < 96)  { int j = tid - 64; sw[6][j] = -rb_wi[j]; sw[7][j] = -rb_bi[j]; sw[8][j] = rb_wo[j]; }
    if (tid >= 96 && tid < 104) sdl[tid - 96] = g_attr_dl[tid - 96];
    __syncthreads();

    int b = blockIdx.x * 256 + tid;
    if (b >= n_batch) return;

    // ego_last fields 0..5 (row stride 51 floats -> alternating parity, scalar loads)
    const float* eg = ego + (size_t)b * (TT * FF) + (TT - 1) * FF;
    float g0 = eg[0], g1 = eg[1], g2 = eg[2], g3 = eg[3], g4 = eg[4], g5 = eg[5];

    // neighbor fields 2..5: float2 where 8B-aligned (parity of n), scalar otherwise
    const float* nb = nei + (size_t)b * (NN * FF);
    float rx[8], ry[8], rnorm[8], bb[8];
    unsigned mbits = 0;
#pragma unroll
    for (int n = 0; n < 8; n++) {
        const float* p = nb + n * FF;
        float a2, a3, a4, a5;
        if (n & 1) {
            a2 = p[2];
            float2 t = *reinterpret_cast<const float2*>(p + 3);
            a3 = t.x; a4 = t.y;
            a5 = p[5];
        } else {
            float2 t = *reinterpret_cast<const float2*>(p + 2);
            float2 u = *reinterpret_cast<const float2*>(p + 4);
            a2 = t.x; a3 = t.y; a4 = u.x; a5 = u.y;
        }
        mbits |= (a2 == 0.f ? 1u : 0u) << (2 * n);
        mbits |= (a3 == 0.f ? 1u : 0u) << (2 * n + 1);
        float rxx = a2 - g2, ryy = a3 - g3;
        rx[n] = rxx; ry[n] = ryy;
        float rn2 = rxx * rxx + ryy * ryy;
        float rnm = sqrtf(rn2);
        rnorm[n] = rnm;
        // b = sqrt(r_norm + |r + v*DT|^2 - |v*DT|^2) / 2   (as written in reference)
        float px = rxx + a4 * DT, py = ryy + a5 * DT;
        float s1 = px * px + py * py;
        float s2 = (a4 * DT) * (a4 * DT) + (a5 * DT) * (a5 * DT);
        bb[n] = sqrtf(rnm + s1 - s2) * 0.5f;
    }

    float rbv0 = g3 - border[0];
    float rbv1 = g3 - border[3];
    float rbn0 = fabsf(rbv0), rbn1 = fabsf(rbv1);

    // Fused MLP evaluation: an(rnorm[8]), rn(bb[8]), rb(rbn0, rbn1)
    float acc_an[8], acc_rn[8];
    float bo_an = an_bo[0], bo_rn = rn_bo[0], bo_rb = rb_bo[0];
#pragma unroll
    for (int n = 0; n < 8; n++) { acc_an[n] = bo_an; acc_rn[n] = bo_rn; }
    float acc_rb0 = bo_rb, acc_rb1 = bo_rb;

#pragma unroll 4
    for (int j = 0; j < 32; j++) {
        float wa = sw[0][j], ba = sw[1][j], oa = sw[2][j];
        float wr = sw[3][j], br = sw[4][j], orr = sw[5][j];
        float wb = sw[6][j], bt = sw[7][j], ob = sw[8][j];
#pragma unroll
        for (int n = 0; n < 8; n++) {
            acc_an[n] = fmaf(oa, fmaxf(fmaf(wa, rnorm[n], ba), 0.f), acc_an[n]);
            acc_rn[n] = fmaf(orr, fmaxf(fmaf(wr, bb[n], br), 0.f), acc_rn[n]);
        }
        acc_rb0 = fmaf(ob, fmaxf(fmaf(wb, rbn0, bt), 0.f), acc_rb0);
        acc_rb1 = fmaf(ob, fmaxf(fmaf(wb, rbn1, bt), 0.f), acc_rb1);
    }

    // e = normalize(ego_last[:,4:6]); angle threshold (division-free compare)
    float einv = rsqrtf(g4 * g4 + g5 * g5);
    float ex = g4 * einv, ey = g5 * einv;
    float na = fmaxf(sqrtf(ex * ex + ey * ey), EPS);
    float thr = eff_angle[0] * na;

    float ax = 0.f, ay = 0.f;

    // f_dest: v34 = (g3, g4); dv = (|v34|, 0)
    {
        float nv = sqrtf(g3 * g3 + g4 * g4);
        float p0 = adp[0], p1 = adp[1];
        float fx = (p1 * nv - g3) / p0;
        float fy = (0.f - g4) / p0;
        float dot = ex * fx + ey * fy;
        float nbn = fmaxf(sqrtf(fx * fx + fy * fy), EPS);
        bool keep = fabsf(dot) > thr * nbn;
        ax += keep ? fx : 0.f;
        ay += keep ? fy : 0.f;
    }

    // f_attr + f_repu per neighbor (mask applied BEFORE angle clamp)
#pragma unroll
    for (int n = 0; n < 8; n++) {
        float inv = 1.0f / rnorm[n];
        bool mx = (mbits >> (2 * n)) & 1u;
        bool my = (mbits >> (2 * n + 1)) & 1u;

        float fac = acc_an[n] * inv * sdl[n];
        float fx = mx ? 0.f : fac * rx[n];
        float fy = my ? 0.f : fac * ry[n];
        float dot = ex * fx + ey * fy;
        float nbn = fmaxf(sqrtf(fx * fx + fy * fy), EPS);
        bool keep = fabsf(dot) > thr * nbn;
        ax += keep ? fx : 0.f;
        ay += keep ? fy : 0.f;

        float fac2 = acc_rn[n] * inv;
        float gx = mx ? 0.f : fac2 * rx[n];
        float gy = my ? 0.f : fac2 * ry[n];
        float dot2 = ex * gx + ey * gy;
        float nb2 = fmaxf(sqrtf(gx * gx + gy * gy), EPS);
        bool keep2 = fabsf(dot2) > thr * nb2;
        ax += keep2 ? gx : 0.f;
        ay += keep2 ? gy : 0.f;
    }

    // f_bor: vectors (0, mono_rb(|rbv_i|) * sign(rbv_i))
    {
        float fy0 = acc_rb0 * (rbv0 / rbn0);
        float nbn0 = fmaxf(fabsf(fy0), EPS);
        bool k0 = fabsf(ey * fy0) > thr * nbn0;
        ay += k0 ? fy0 : 0.f;

        float fy1 = acc_rb1 * (rbv1 / rbn1);
        float nbn1 = fmaxf(fabsf(fy1), EPS);
        bool k1 = fabsf(ey * fy1) > thr * nbn1;
        ay += k1 ? fy1 : 0.f;
    }

    float vxo = g2 + ax * DT;
    float vyo = g3 + ay * DT;
    float sx = g0 + vxo * DT;
    float sy = g1 + vyo * DT;

    float2* o = reinterpret_cast<float2*>(out + (size_t)b * 6);  // 24B stride, 8B aligned
    o[0] = make_float2(sx, sy);
    o[1] = make_float2(vxo, vyo);
    o[2] = make_float2(ax, ay);
}

extern "C" void kernel_launch(void* const* d_in, const int* in_sizes, int n_in,
                              void* d_out, int out_size)
{
    const float* ego    = (const float*)d_in[0];
    const float* nei    = (const float*)d_in[1];
    const float* border = (const float*)d_in[2];
    const float* adp    = (const float*)d_in[3];
    const float* eff    = (const float*)d_in[4];
    const float* an_wi  = (const float*)d_in[5];
    const float* an_bi  = (const float*)d_in[6];
    const float* an_wo  = (const float*)d_in[7];
    const float* an_bo  = (const float*)d_in[8];
    const float* rn_wi  = (const float*)d_in[9];
    const float* rn_bi  = (const float*)d_in[10];
    const float* rn_wo  = (const float*)d_in[11];
    const float* rn_bo  = (const float*)d_in[12];
    const float* rb_wi  = (const float*)d_in[13];
    const float* rb_bi  = (const float*)d_in[14];
    const float* rb_wo  = (const float*)d_in[15];
    const float* rb_bo  = (const float*)d_in[16];
    const float* dl_wi  = (const float*)d_in[17];
    const float* dl_bi  = (const float*)d_in[18];
    const float* dl_wo  = (const float*)d_in[19];
    const float* dl_bo  = (const float*)d_in[20];
    float* out = (float*)d_out;

    int n_batch = in_sizes[0] / (TT * FF);

    sfm_precompute<<<1, 8>>>(ego, dl_wi, dl_bi, dl_wo, dl_bo);

    int blocks = (n_batch + 255) / 256;
    sfm_main<<<blocks, 256>>>(ego, nei, border, adp, eff,
                              an_wi, an_bi, an_wo, an_bo,
                              rn_wi, rn_bi, rn_wo, rn_bo,
                              rb_wi, rb_bi, rb_wo, rb_bo,
                              out, n_batch);
}